// round 11
// baseline (speedup 1.0000x reference)
#include <cuda_runtime.h>
#include <math.h>
#include <stdint.h>

#define LSEQ 1024
#define DM   1024
#define DI   2048
#define DS   16
#define DTR  64

// ---------------- scratch (device globals; no runtime allocation) ----------------
__device__ __align__(16) float g_xz[2][LSEQ][2*DI];       // in_proj output (xi | z)
__device__ __align__(16) float g_u [2][LSEQ][DI];         // conv+silu output
__device__ __align__(16) float g_xdbl_part[2][16][LSEQ][96];
__device__ __align__(16) float g_xdbl[2][LSEQ][96];       // [dt(64) | B(16) | C(16)]
__device__ __align__(16) float g_delta[2][LSEQ][DI];
__device__ __align__(16) float g_cat[LSEQ][2*DM];         // [out_fw | out_bw] row-major
__device__ __align__(16) float g_lnin[LSEQ][DM];          // pre-LN final proj

// k-major (transposed) operands for cp.async GEMMs
__device__ __align__(16) float g_xT   [DM][LSEQ];         // x^T
__device__ __align__(16) float g_xrevT[DM][LSEQ];         // x^T with rows of x reversed
__device__ __align__(16) float g_inwT [2][DM * 2 * DI];   // in_w^T  [1024][4096]
__device__ __align__(16) float g_outwT[2][DI * DM];       // out_w^T [2048][1024]
__device__ __align__(16) float g_pwT  [2 * DM * DM];      // proj_w^T [2048][1024]
__device__ __align__(16) float g_dtwT [2][DTR * DI];      // dt_w^T  [64][2048]
__device__ __align__(16) float g_xdT  [2][DTR][LSEQ];     // x_dbl^T (dt cols only)
__device__ __align__(16) float g_y2T  [2][DI][LSEQ];      // y2^T
__device__ __align__(16) float g_catT [2 * DM][LSEQ];     // cat^T

__device__ __forceinline__ float sigmoid_f(float x) {
    return __fdividef(1.f, 1.f + __expf(-x));
}
__device__ __forceinline__ float softplus_f(float x) {
    return (x > 20.f) ? x : log1pf(__expf(x));
}

// ---------------- packed f32x2 helpers ----------------
typedef unsigned long long u64t;
__device__ __forceinline__ u64t pack2(float lo, float hi) {
    u64t r;
    asm("mov.b64 %0, {%1, %2};" : "=l"(r) : "r"(__float_as_uint(lo)), "r"(__float_as_uint(hi)));
    return r;
}
__device__ __forceinline__ void unpack2(u64t v, float& lo, float& hi) {
    uint32_t a, b;
    asm("mov.b64 {%0, %1}, %2;" : "=r"(a), "=r"(b) : "l"(v));
    lo = __uint_as_float(a);
    hi = __uint_as_float(b);
}
#define FFMA2(d, a, b, c) \
    asm("fma.rn.f32x2 %0, %1, %2, %3;" : "=l"(d) : "l"(a), "l"(b), "l"(c))

// ---------------- cp.async helpers (sm_80+ base ISA) ----------------
__device__ __forceinline__ uint32_t smem_u32(const void* p) {
    return (uint32_t)__cvta_generic_to_shared(p);
}
#define CP_ASYNC16(dst, src) \
    asm volatile("cp.async.cg.shared.global [%0], [%1], 16;" :: "r"(dst), "l"(src) : "memory")
#define CP_COMMIT() asm volatile("cp.async.commit_group;" ::: "memory")
#define CP_WAIT1()  asm volatile("cp.async.wait_group 1;" ::: "memory")
#define CP_WAIT0()  asm volatile("cp.async.wait_group 0;" ::: "memory")

// ---------------- profiling anchor ----------------
__global__ void noop_kernel() {}

// ---------------- transpose_all: produce all k-major operands in one launch ----------------
__global__ void __launch_bounds__(256)
transpose_all(const float* __restrict__ x,
              const float* __restrict__ inwf, const float* __restrict__ inwb,
              const float* __restrict__ outwf, const float* __restrict__ outwb,
              const float* __restrict__ pw,
              const float* __restrict__ dtwf, const float* __restrict__ dtwb)
{
    __shared__ float t[32][33];
    int b = blockIdx.x;
    const float* S; float* D; int R, Cc; int rev = 0;
    if (b < 2048) {
        S = x; R = 1024; Cc = 1024;
        if (b < 1024) { D = &g_xT[0][0]; }
        else          { D = &g_xrevT[0][0]; rev = 1; b -= 1024; }
    } else if (b < 10240) {
        R = 4096; Cc = 1024;
        if (b < 6144) { S = inwf; D = g_inwT[0]; b -= 2048; }
        else          { S = inwb; D = g_inwT[1]; b -= 6144; }
    } else if (b < 14336) {
        R = 1024; Cc = 2048;
        if (b < 12288) { S = outwf; D = g_outwT[0]; b -= 10240; }
        else           { S = outwb; D = g_outwT[1]; b -= 12288; }
    } else if (b < 16384) {
        S = pw; D = g_pwT; R = 1024; Cc = 2048; b -= 14336;
    } else {
        R = 2048; Cc = 64;
        if (b < 16512) { S = dtwf; D = g_dtwT[0]; b -= 16384; }
        else           { S = dtwb; D = g_dtwT[1]; b -= 16512; }
    }
    int tpr = Cc >> 5;
    int by = b / tpr, bx = b % tpr;
    int r0 = by << 5, c0 = bx << 5;
    int tj  = threadIdx.x & 31;
    int ti4 = (threadIdx.x >> 5) << 2;
#pragma unroll
    for (int i = 0; i < 4; i++)
        t[ti4 + i][tj] = S[(size_t)(r0 + ti4 + i) * Cc + c0 + tj];
    __syncthreads();
    if (!rev) {
#pragma unroll
        for (int i = 0; i < 4; i++)
            D[(size_t)(c0 + ti4 + i) * R + r0 + tj] = t[tj][ti4 + i];
    } else {
#pragma unroll
        for (int i = 0; i < 4; i++)
            D[(size_t)(c0 + ti4 + i) * R + (R - 1 - (r0 + tj))] = t[tj][ti4 + i];
    }
}

// ---------------- transpose_cat: cat[1024][2048] -> catT[2048][1024] ----------------
__global__ void __launch_bounds__(256)
transpose_cat()
{
    __shared__ float t[32][33];
    int b  = blockIdx.x;              // 32 x 64 tiles = 2048
    int by = b >> 6, bx = b & 63;
    int r0 = by << 5, c0 = bx << 5;
    int tj  = threadIdx.x & 31;
    int ti4 = (threadIdx.x >> 5) << 2;
#pragma unroll
    for (int i = 0; i < 4; i++)
        t[ti4 + i][tj] = g_cat[r0 + ti4 + i][c0 + tj];
    __syncthreads();
#pragma unroll
    for (int i = 0; i < 4; i++)
        g_catT[c0 + ti4 + i][r0 + tj] = t[tj][ti4 + i];
}

// ---------------- NT SGEMM, f32x2, cp.async 3-stage pipeline, ONE barrier per K-step ----------------
// C(MxN) = A(MxK) * W(NxK)^T, A/W given TRANSPOSED (k-major): A_T[K][ldm], W_T[K][ldn].
// dir = blockIdx.z selects Af/Ab, Wf/Wb, bias; cdoff = linear C offset per dir.
// BN=128 fixed, TN=8; TM=BM/16; crevd flips output row for dir=1.
// epi: 0 plain, 1 softplus(acc+bias), 2 acc+resid, 3 acc+bias
template<int BM, int BK, int MINB>
__global__ void __launch_bounds__(256, MINB)
sgemm_ca(const float* __restrict__ Af, const float* __restrict__ Ab, int ldm,
         const float* __restrict__ Wf, const float* __restrict__ Wb, int ldn,
         float* __restrict__ C, size_t cdoff, int ldc, int crevd,
         int M, int K, int epi,
         const float* __restrict__ biasf, const float* __restrict__ biasb,
         const float* __restrict__ resid, int ldr)
{
    constexpr int BN = 128;
    constexpr int TM = BM / 16;
    constexpr int NAc = (BM * BK) / 1024;  // A cp.asyncs per thread per stage
    constexpr int NBc = BK / 8;            // B cp.asyncs per thread per stage
    constexpr int ST = 3;
    __shared__ __align__(16) float As[ST][BK][BM + 4];
    __shared__ __align__(16) float Bs[ST][BK][BN + 8];

    const int dir = blockIdx.z;
    const float* A    = dir ? Ab : Af;
    const float* W    = dir ? Wb : Wf;
    const float* bias = dir ? biasb : biasf;
    const int crev = crevd & -dir;
    const size_t cdo = (size_t)dir * cdoff;

    const int tid  = threadIdx.x;
    const int row0 = blockIdx.y * BM;
    const int col0 = blockIdx.x * BN;
    const int tx   = tid & 15;
    const int ty   = tid >> 4;

    u64t acc2[TM][4];
#pragma unroll
    for (int i = 0; i < TM; i++)
#pragma unroll
        for (int j = 0; j < 4; j++) acc2[i][j] = 0ull;

    auto issue = [&](int ki, int buf) {
        const int kb = ki * BK;
#pragma unroll
        for (int l = 0; l < NAc; l++) {
            int fi = tid + l * 256;
            int kk = fi / (BM / 4);
            int mc = fi % (BM / 4);
            uint32_t dst = smem_u32(&As[buf][kk][mc * 4]);
            const float* src = A + (size_t)(kb + kk) * ldm + row0 + mc * 4;
            CP_ASYNC16(dst, src);
        }
#pragma unroll
        for (int l = 0; l < NBc; l++) {
            int fi = tid + l * 256;
            int kk = fi >> 5, m = fi & 31;
            uint32_t dst = smem_u32(&Bs[buf][kk][(m >> 1) * 4 + (m & 1) * 64]);
            const float* src = W + (size_t)(kb + kk) * ldn + col0 + m * 4;
            CP_ASYNC16(dst, src);
        }
        CP_COMMIT();
    };

    const int nk = K / BK;
    issue(0, 0);
    if (nk > 1) issue(1, 1);

    for (int ki = 0; ki < nk; ki++) {
        if (ki + 1 < nk) { CP_WAIT1(); } else { CP_WAIT0(); }
        __syncthreads();
        // safe without trailing barrier: target buf (ki+2)%3 == (ki-1)%3 was
        // fully consumed in iter ki-1; every warp passed this iter's barrier
        // only after finishing that compute.
        if (ki + 2 < nk) issue(ki + 2, (ki + 2) % ST);
        const int cur = ki % ST;
#pragma unroll
        for (int kk = 0; kk < BK; kk++) {
            float a[TM];
#pragma unroll
            for (int i = 0; i < TM; i += 4)
                *reinterpret_cast<float4*>(&a[i]) =
                    *reinterpret_cast<const float4*>(&As[cur][kk][ty * TM + i]);
            u64t b2[4];
            {
                ulonglong2 bv0 = *reinterpret_cast<const ulonglong2*>(&Bs[cur][kk][tx * 4]);
                ulonglong2 bv1 = *reinterpret_cast<const ulonglong2*>(&Bs[cur][kk][64 + tx * 4]);
                b2[0] = bv0.x; b2[1] = bv0.y;
                b2[2] = bv1.x; b2[3] = bv1.y;
            }
#pragma unroll
            for (int i = 0; i < TM; i++) {
                u64t a2 = pack2(a[i], a[i]);
#pragma unroll
                for (int j = 0; j < 4; j++)
                    FFMA2(acc2[i][j], a2, b2[j], acc2[i][j]);
            }
        }
    }

#pragma unroll
    for (int i = 0; i < TM; i++) {
        int lr = row0 + ty * TM + i;
        int pr = crev ? (M - 1 - lr) : lr;
#pragma unroll
        for (int j = 0; j < 4; j++) {
            float v0, v1;
            unpack2(acc2[i][j], v0, v1);
            int c0 = col0 + tx * 8 + j * 2;
            if (epi == 1) {
                v0 = softplus_f(v0 + bias[c0]);
                v1 = softplus_f(v1 + bias[c0 + 1]);
            } else if (epi == 2) {
                v0 += resid[(size_t)pr * ldr + c0];
                v1 += resid[(size_t)pr * ldr + c0 + 1];
            } else if (epi == 3) {
                v0 += bias[c0];
                v1 += bias[c0 + 1];
            }
            C[cdo + (size_t)pr * ldc + c0]     = v0;
            C[cdo + (size_t)pr * ldc + c0 + 1] = v1;
        }
    }
}

// ---------------- causal depthwise conv (4 taps) + SiLU ----------------
__global__ void conv_silu_kernel(const float* __restrict__ cwf, const float* __restrict__ cbf,
                                 const float* __restrict__ cwb, const float* __restrict__ cbb)
{
    int idx = blockIdx.x * blockDim.x + threadIdx.x;
    int d   = idx & (DI - 1);
    int t   = (idx >> 11) & (LSEQ - 1);
    int dir = idx >> 21;
    const float* cw = dir ? cwb : cwf;
    const float* cb = dir ? cbb : cbf;
    float w0 = cw[d * 4 + 0], w1 = cw[d * 4 + 1], w2 = cw[d * 4 + 2], w3 = cw[d * 4 + 3];
    const float* xi = &g_xz[dir][0][d];
    float acc = cb[d];
    if (t >= 3) acc += w0 * xi[(t - 3) * (2 * DI)];
    if (t >= 2) acc += w1 * xi[(t - 2) * (2 * DI)];
    if (t >= 1) acc += w2 * xi[(t - 1) * (2 * DI)];
    acc += w3 * xi[t * (2 * DI)];
    g_u[dir][t][d] = acc * sigmoid_f(acc);
}

// ---------------- x-proj: x_dbl = u @ xproj_w^T, 16-way split-K ----------------
__global__ void __launch_bounds__(256)
xproj_partial_kernel(const float* __restrict__ wf, const float* __restrict__ wb)
{
    const int chunk = blockIdx.x;
    const int mb    = blockIdx.y;
    const int dir   = blockIdx.z;
    const float* W  = dir ? wb : wf;
    const int row0  = mb * 32;
    const int kbase = chunk * 128;
    const int tid   = threadIdx.x;

    __shared__ __align__(16) float Us[32][36];
    __shared__ __align__(16) float Ws[32][100];

    const int tx = tid & 15;
    const int ty = tid >> 4;
    float acc[2][6];
#pragma unroll
    for (int i = 0; i < 2; i++)
#pragma unroll
        for (int j = 0; j < 6; j++) acc[i][j] = 0.f;

#pragma unroll
    for (int k0 = 0; k0 < 128; k0 += 32) {
        {
            int r  = tid >> 3;
            int kk = (tid & 7) << 2;
            float4 v = *reinterpret_cast<const float4*>(&g_u[dir][row0 + r][kbase + k0 + kk]);
            Us[kk + 0][r] = v.x; Us[kk + 1][r] = v.y;
            Us[kk + 2][r] = v.z; Us[kk + 3][r] = v.w;
        }
#pragma unroll
        for (int l = 0; l < 3; l++) {
            int fi = tid + l * 256;
            int n  = fi >> 3;
            int kk = (fi & 7) << 2;
            float4 v = *reinterpret_cast<const float4*>(&W[(size_t)n * DI + kbase + k0 + kk]);
            Ws[kk + 0][n] = v.x; Ws[kk + 1][n] = v.y;
            Ws[kk + 2][n] = v.z; Ws[kk + 3][n] = v.w;
        }
        __syncthreads();
#pragma unroll
        for (int kk = 0; kk < 32; kk++) {
            float a0 = Us[kk][ty * 2 + 0];
            float a1 = Us[kk][ty * 2 + 1];
#pragma unroll
            for (int j = 0; j < 6; j++) {
                float bv = Ws[kk][tx * 6 + j];
                acc[0][j] = fmaf(a0, bv, acc[0][j]);
                acc[1][j] = fmaf(a1, bv, acc[1][j]);
            }
        }
        __syncthreads();
    }
#pragma unroll
    for (int i = 0; i < 2; i++)
#pragma unroll
        for (int j = 0; j < 6; j++)
            g_xdbl_part[dir][chunk][row0 + ty * 2 + i][tx * 6 + j] = acc[i][j];
}

__global__ void xdbl_reduce_kernel()
{
    int idx = blockIdx.x * blockDim.x + threadIdx.x;   // 2*1024*96
    int c   = idx % 96;
    int t   = (idx / 96) & (LSEQ - 1);
    int dir = idx / (96 * LSEQ);
    float s = 0.f;
#pragma unroll
    for (int ch = 0; ch < 16; ch++) s += g_xdbl_part[dir][ch][t][c];
    g_xdbl[dir][t][c] = s;
    if (c < DTR) g_xdT[dir][c][t] = s;   // k-major copy for the dt GEMM
}

// ---------------- selective scan: 4-step chunked register prefetch ----------------
__global__ void __launch_bounds__(128)
scan_kernel(const float* __restrict__ Alf, const float* __restrict__ Dpf,
            const float* __restrict__ Alb, const float* __restrict__ Dpb)
{
    int gid = blockIdx.x * 128 + threadIdx.x;   // 16384 total
    int q   = gid & 3;
    int grp = gid >> 2;
    int dir = grp >> 11;
    int d   = grp & (DI - 1);

    const float* Alog = dir ? Alb : Alf;
    float dp = (dir ? Dpb : Dpf)[d];
    float Aa[4];
#pragma unroll
    for (int j = 0; j < 4; j++) Aa[j] = -expf(Alog[d * DS + q * 4 + j]);

    const float* dep = &g_delta[dir][0][d];
    const float* up  = &g_u[dir][0][d];
    const float* zp  = &g_xz[dir][0][DI + d];
    const float* bcp = &g_xdbl[dir][0][DTR + q * 4];
    float* ypT = &g_y2T[dir][d][0];

    float h0 = 0.f, h1 = 0.f, h2 = 0.f, h3 = 0.f;

    float dA[4], uA[4], zA[4]; float4 BA[4], CA[4];
    float dB[4], uB[4], zB[4]; float4 BB[4], CB[4];

#define LOADCH(t0, dv, uv, zv, Bv, Cv) do {                                   \
    _Pragma("unroll")                                                         \
    for (int i = 0; i < 4; i++) {                                             \
        dv[i] = dep[((t0) + i) * DI];                                         \
        uv[i] = up [((t0) + i) * DI];                                         \
        zv[i] = zp [((t0) + i) * (2 * DI)];                                   \
        Bv[i] = *reinterpret_cast<const float4*>(bcp + ((t0) + i) * 96);      \
        Cv[i] = *reinterpret_cast<const float4*>(bcp + ((t0) + i) * 96 + DS); \
    } } while (0)

#define COMPCH(t0, dv, uv, zv, Bv, Cv) do {                                   \
    float yout[4];                                                            \
    _Pragma("unroll")                                                         \
    for (int i = 0; i < 4; i++) {                                             \
        float dc = dv[i], uc = uv[i], zc = zv[i];                             \
        float4 Bc = Bv[i], Cc = Cv[i];                                        \
        float db = dc * uc;                                                   \
        float e0 = __expf(dc * Aa[0]);                                        \
        float e1 = __expf(dc * Aa[1]);                                        \
        float e2 = __expf(dc * Aa[2]);                                        \
        float e3 = __expf(dc * Aa[3]);                                        \
        h0 = fmaf(e0, h0, db * Bc.x);                                         \
        h1 = fmaf(e1, h1, db * Bc.y);                                         \
        h2 = fmaf(e2, h2, db * Bc.z);                                         \
        h3 = fmaf(e3, h3, db * Bc.w);                                         \
        float p = h0 * Cc.x + h1 * Cc.y + h2 * Cc.z + h3 * Cc.w;              \
        p += __shfl_xor_sync(0xffffffffu, p, 1);                              \
        p += __shfl_xor_sync(0xffffffffu, p, 2);                              \
        if (q == 0) yout[i] = (p + uc * dp) * zc * sigmoid_f(zc);             \
    }                                                                         \
    if (q == 0) {                                                             \
        float4 v; v.x = yout[0]; v.y = yout[1]; v.z = yout[2]; v.w = yout[3]; \
        *reinterpret_cast<float4*>(ypT + (t0)) = v;                           \
    } } while (0)

    LOADCH(0, dA, uA, zA, BA, CA);
    for (int c = 0; c < LSEQ / 4; c += 2) {
        if (c + 1 < LSEQ / 4) LOADCH((c + 1) * 4, dB, uB, zB, BB, CB);
        COMPCH(c * 4, dA, uA, zA, BA, CA);
        if (c + 2 < LSEQ / 4) LOADCH((c + 2) * 4, dA, uA, zA, BA, CA);
        COMPCH((c + 1) * 4, dB, uB, zB, BB, CB);
    }
#undef LOADCH
#undef COMPCH
}

// ---------------- layernorm over rows of g_lnin -> out ----------------
__global__ void __launch_bounds__(256)
layernorm_kernel(const float* __restrict__ lw, const float* __restrict__ lb,
                 float* __restrict__ out)
{
    int row = blockIdx.x;
    const float* v = g_lnin[row];
    float s = 0.f, s2 = 0.f;
#pragma unroll
    for (int l = 0; l < 4; l++) {
        float x = v[threadIdx.x + l * 256];
        s += x; s2 += x * x;
    }
#pragma unroll
    for (int o = 16; o > 0; o >>= 1) {
        s  += __shfl_xor_sync(0xffffffffu, s,  o);
        s2 += __shfl_xor_sync(0xffffffffu, s2, o);
    }
    __shared__ float sm1[8], sm2[8];
    __shared__ float mu_s, rs_s;
    int w = threadIdx.x >> 5;
    if ((threadIdx.x & 31) == 0) { sm1[w] = s; sm2[w] = s2; }
    __syncthreads();
    if (threadIdx.x == 0) {
        float S = 0.f, S2 = 0.f;
#pragma unroll
        for (int i = 0; i < 8; i++) { S += sm1[i]; S2 += sm2[i]; }
        float mu  = S * (1.f / DM);
        float var = S2 * (1.f / DM) - mu * mu;
        mu_s = mu;
        rs_s = rsqrtf(var + 1e-5f);
    }
    __syncthreads();
    float mu = mu_s, rs = rs_s;
#pragma unroll
    for (int l = 0; l < 4; l++) {
        int i = threadIdx.x + l * 256;
        float x = v[i];
        out[(size_t)row * DM + i] = (x - mu) * rs * lw[i] + lb[i];
    }
}

// ---------------- launch ----------------
extern "C" void kernel_launch(void* const* d_in, const int* in_sizes, int n_in,
                              void* d_out, int out_size)
{
    const float* x         = (const float*)d_in[0];
    const float* fw_in_w   = (const float*)d_in[1];
    const float* fw_conv_w = (const float*)d_in[2];
    const float* fw_conv_b = (const float*)d_in[3];
    const float* fw_xproj  = (const float*)d_in[4];
    const float* fw_dt_w   = (const float*)d_in[5];
    const float* fw_dt_b   = (const float*)d_in[6];
    const float* fw_Alog   = (const float*)d_in[7];
    const float* fw_Dp     = (const float*)d_in[8];
    const float* fw_out_w  = (const float*)d_in[9];
    const float* bw_in_w   = (const float*)d_in[10];
    const float* bw_conv_w = (const float*)d_in[11];
    const float* bw_conv_b = (const float*)d_in[12];
    const float* bw_xproj  = (const float*)d_in[13];
    const float* bw_dt_w   = (const float*)d_in[14];
    const float* bw_dt_b   = (const float*)d_in[15];
    const float* bw_Alog   = (const float*)d_in[16];
    const float* bw_Dp     = (const float*)d_in[17];
    const float* bw_out_w  = (const float*)d_in[18];
    const float* proj_w    = (const float*)d_in[19];
    const float* proj_b    = (const float*)d_in[20];
    const float* ln_w      = (const float*)d_in[21];
    const float* ln_b      = (const float*)d_in[22];
    float* out = (float*)d_out;

    float *xz, *del, *lnin, *xT, *xrevT, *inwT, *outwT, *pwT, *dtwT, *xdT, *y2T, *cat, *catT;
    cudaGetSymbolAddress((void**)&xz,    g_xz);
    cudaGetSymbolAddress((void**)&del,   g_delta);
    cudaGetSymbolAddress((void**)&lnin,  g_lnin);
    cudaGetSymbolAddress((void**)&xT,    g_xT);
    cudaGetSymbolAddress((void**)&xrevT, g_xrevT);
    cudaGetSymbolAddress((void**)&inwT,  g_inwT);
    cudaGetSymbolAddress((void**)&outwT, g_outwT);
    cudaGetSymbolAddress((void**)&pwT,   g_pwT);
    cudaGetSymbolAddress((void**)&dtwT,  g_dtwT);
    cudaGetSymbolAddress((void**)&xdT,   g_xdT);
    cudaGetSymbolAddress((void**)&y2T,   g_y2T);
    cudaGetSymbolAddress((void**)&cat,   g_cat);
    cudaGetSymbolAddress((void**)&catT,  g_catT);

    const size_t INW = (size_t)DM * 2 * DI;
    const size_t OUTW = (size_t)DI * DM;
    const size_t DTW = (size_t)DTR * DI;
    const size_t XDT = (size_t)DTR * LSEQ;
    const size_t Y2T = (size_t)DI * LSEQ;

    // 0) all input transposes in one launch
    transpose_all<<<16640, 256>>>(x, fw_in_w, bw_in_w, fw_out_w, bw_out_w,
                                  proj_w, fw_dt_w, bw_dt_w);
    // 1,2) anchors so in_proj sits at profiler capture point (idx 3)
    noop_kernel<<<1, 32>>>();
    noop_kernel<<<1, 32>>>();

    // 3) in_proj: (M=1024, N=4096, K=1024), fw+bw merged — BK=32, 1 barrier/step
    sgemm_ca<128,32,2><<<dim3(32, 8, 2), 256>>>(
        xT, xrevT, LSEQ, inwT, inwT + INW, 2 * DI,
        xz, (size_t)LSEQ * 2 * DI, 2 * DI, 0,
        LSEQ, DM, 0, nullptr, nullptr, nullptr, 0);

    // 4) conv + silu -> u
    conv_silu_kernel<<<(2 * LSEQ * DI) / 256, 256>>>(fw_conv_w, fw_conv_b, bw_conv_w, bw_conv_b);

    // 5) x-proj (16-way split-K) -> x_dbl (+ k-major dt cols)
    dim3 gx(16, 32, 2);
    xproj_partial_kernel<<<gx, 256>>>(fw_xproj, bw_xproj);
    xdbl_reduce_kernel<<<(2 * LSEQ * 96) / 256, 256>>>();

    // 6) delta = softplus(dt @ dt_w^T + dt_b)  (M=1024, N=2048, K=64)
    sgemm_ca<128,32,2><<<dim3(16, 8, 2), 256>>>(
        xdT, xdT + XDT, LSEQ, dtwT, dtwT + DTW, DI,
        del, (size_t)LSEQ * DI, DI, 0,
        LSEQ, DTR, 1, fw_dt_b, bw_dt_b, nullptr, 0);

    // 7) selective scan -> y2^T
    scan_kernel<<<128, 128>>>(fw_Alog, fw_Dp, bw_Alog, bw_Dp);

    // 8) out_proj + residual -> cat (row-major coalesced; bw rows flipped, +DM col offset)
    sgemm_ca<64,16,3><<<dim3(8, 16, 2), 256>>>(
        y2T, y2T + Y2T, LSEQ, outwT, outwT + OUTW, DM,
        cat, (size_t)DM, 2 * DM, 1,
        LSEQ, DI, 2, nullptr, nullptr, x, DM);

    // 9) cat -> catT (tiled, coalesced both sides)
    transpose_cat<<<2048, 256>>>();

    // 10) final proj: lnin = cat @ proj_w^T + proj_b  (M=1024, N=1024, K=2048)
    sgemm_ca<64,16,3><<<dim3(8, 16, 1), 256>>>(
        catT, catT, LSEQ, pwT, pwT, DM,
        lnin, 0, DM, 0,
        LSEQ, 2 * DM, 3, proj_b, proj_b, nullptr, 0);

    // 11) layernorm -> out
    layernorm_kernel<<<LSEQ, 256>>>(ln_w, ln_b, out);
}

// round 12
// speedup vs baseline: 1.0442x; 1.0442x over previous
#include <cuda_runtime.h>
#include <math.h>
#include <stdint.h>

#define LSEQ 1024
#define DM   1024
#define DI   2048
#define DS   16
#define DTR  64

// ---------------- scratch (device globals; no runtime allocation) ----------------
__device__ __align__(16) float g_xz[2][LSEQ][2*DI];       // in_proj output (xi | z)
__device__ __align__(16) float g_u [2][LSEQ][DI];         // conv+silu output
__device__ __align__(16) float g_xdbl_part[2][16][LSEQ][96];
__device__ __align__(16) float g_xdbl[2][LSEQ][96];       // [dt(64) | B(16) | C(16)]
__device__ __align__(16) float g_delta[2][LSEQ][DI];
__device__ __align__(16) float g_cat[LSEQ][2*DM];         // [out_fw | out_bw] row-major
__device__ __align__(16) float g_opart[2][2][LSEQ][DM];   // out_proj split-K partials
__device__ __align__(16) float g_fpart[4][LSEQ][DM];      // final proj split-K partials

// k-major (transposed) operands for cp.async GEMMs
__device__ __align__(16) float g_xT   [DM][LSEQ];         // x^T
__device__ __align__(16) float g_xrevT[DM][LSEQ];         // x^T with rows of x reversed
__device__ __align__(16) float g_inwT [2][DM * 2 * DI];   // in_w^T  [1024][4096]
__device__ __align__(16) float g_outwT[2][DI * DM];       // out_w^T [2048][1024]
__device__ __align__(16) float g_pwT  [2 * DM * DM];      // proj_w^T [2048][1024]
__device__ __align__(16) float g_dtwT [2][DTR * DI];      // dt_w^T  [64][2048]
__device__ __align__(16) float g_xdT  [2][DTR][LSEQ];     // x_dbl^T (dt cols only)
__device__ __align__(16) float g_y2T  [2][DI][LSEQ];      // y2^T
__device__ __align__(16) float g_catT [2 * DM][LSEQ];     // cat^T

__device__ __forceinline__ float sigmoid_f(float x) {
    return __fdividef(1.f, 1.f + __expf(-x));
}
__device__ __forceinline__ float softplus_f(float x) {
    return (x > 20.f) ? x : log1pf(__expf(x));
}

// ---------------- packed f32x2 helpers ----------------
typedef unsigned long long u64t;
__device__ __forceinline__ u64t pack2(float lo, float hi) {
    u64t r;
    asm("mov.b64 %0, {%1, %2};" : "=l"(r) : "r"(__float_as_uint(lo)), "r"(__float_as_uint(hi)));
    return r;
}
__device__ __forceinline__ void unpack2(u64t v, float& lo, float& hi) {
    uint32_t a, b;
    asm("mov.b64 {%0, %1}, %2;" : "=r"(a), "=r"(b) : "l"(v));
    lo = __uint_as_float(a);
    hi = __uint_as_float(b);
}
#define FFMA2(d, a, b, c) \
    asm("fma.rn.f32x2 %0, %1, %2, %3;" : "=l"(d) : "l"(a), "l"(b), "l"(c))

// ---------------- cp.async helpers (sm_80+ base ISA) ----------------
__device__ __forceinline__ uint32_t smem_u32(const void* p) {
    return (uint32_t)__cvta_generic_to_shared(p);
}
#define CP_ASYNC16(dst, src) \
    asm volatile("cp.async.cg.shared.global [%0], [%1], 16;" :: "r"(dst), "l"(src) : "memory")
#define CP_COMMIT() asm volatile("cp.async.commit_group;" ::: "memory")
#define CP_WAIT1()  asm volatile("cp.async.wait_group 1;" ::: "memory")
#define CP_WAIT0()  asm volatile("cp.async.wait_group 0;" ::: "memory")

// ---------------- profiling anchor ----------------
__global__ void noop_kernel() {}

// ---------------- transpose_all: produce all k-major operands in one launch ----------------
__global__ void __launch_bounds__(256)
transpose_all(const float* __restrict__ x,
              const float* __restrict__ inwf, const float* __restrict__ inwb,
              const float* __restrict__ outwf, const float* __restrict__ outwb,
              const float* __restrict__ pw,
              const float* __restrict__ dtwf, const float* __restrict__ dtwb)
{
    __shared__ float t[32][33];
    int b = blockIdx.x;
    const float* S; float* D; int R, Cc; int rev = 0;
    if (b < 2048) {
        S = x; R = 1024; Cc = 1024;
        if (b < 1024) { D = &g_xT[0][0]; }
        else          { D = &g_xrevT[0][0]; rev = 1; b -= 1024; }
    } else if (b < 10240) {
        R = 4096; Cc = 1024;
        if (b < 6144) { S = inwf; D = g_inwT[0]; b -= 2048; }
        else          { S = inwb; D = g_inwT[1]; b -= 6144; }
    } else if (b < 14336) {
        R = 1024; Cc = 2048;
        if (b < 12288) { S = outwf; D = g_outwT[0]; b -= 10240; }
        else           { S = outwb; D = g_outwT[1]; b -= 12288; }
    } else if (b < 16384) {
        S = pw; D = g_pwT; R = 1024; Cc = 2048; b -= 14336;
    } else {
        R = 2048; Cc = 64;
        if (b < 16512) { S = dtwf; D = g_dtwT[0]; b -= 16384; }
        else           { S = dtwb; D = g_dtwT[1]; b -= 16512; }
    }
    int tpr = Cc >> 5;
    int by = b / tpr, bx = b % tpr;
    int r0 = by << 5, c0 = bx << 5;
    int tj  = threadIdx.x & 31;
    int ti4 = (threadIdx.x >> 5) << 2;
#pragma unroll
    for (int i = 0; i < 4; i++)
        t[ti4 + i][tj] = S[(size_t)(r0 + ti4 + i) * Cc + c0 + tj];
    __syncthreads();
    if (!rev) {
#pragma unroll
        for (int i = 0; i < 4; i++)
            D[(size_t)(c0 + ti4 + i) * R + r0 + tj] = t[tj][ti4 + i];
    } else {
#pragma unroll
        for (int i = 0; i < 4; i++)
            D[(size_t)(c0 + ti4 + i) * R + (R - 1 - (r0 + tj))] = t[tj][ti4 + i];
    }
}

// ---------------- transpose_cat: cat[1024][2048] -> catT[2048][1024] ----------------
__global__ void __launch_bounds__(256)
transpose_cat()
{
    __shared__ float t[32][33];
    int b  = blockIdx.x;              // 32 x 64 tiles = 2048
    int by = b >> 6, bx = b & 63;
    int r0 = by << 5, c0 = bx << 5;
    int tj  = threadIdx.x & 31;
    int ti4 = (threadIdx.x >> 5) << 2;
#pragma unroll
    for (int i = 0; i < 4; i++)
        t[ti4 + i][tj] = g_cat[r0 + ti4 + i][c0 + tj];
    __syncthreads();
#pragma unroll
    for (int i = 0; i < 4; i++)
        g_catT[c0 + ti4 + i][r0 + tj] = t[tj][ti4 + i];
}

// ---------------- NT SGEMM, f32x2, cp.async 3-stage pipeline, split-K capable ----------------
// C(MxN) = A(MxK) * W(NxK)^T, A/W given TRANSPOSED (k-major): A_T[K][ldm], W_T[K][ldn].
// blockIdx.z = dir*nsplit + s.  A/W offset by s*K rows (K = per-split depth).
// C offset = dir*cdoff + s*sdoff.  BN=128, TM=BM/16, TN=8.
// epi: 0 plain, 1 softplus(acc+bias), 2 acc+resid, 3 acc+bias
template<int BM, int BK, int MINB>
__global__ void __launch_bounds__(256, MINB)
sgemm_ca(const float* __restrict__ Af, const float* __restrict__ Ab, int ldm,
         const float* __restrict__ Wf, const float* __restrict__ Wb, int ldn,
         float* __restrict__ C, size_t cdoff, size_t sdoff, int nsplit,
         int ldc, int crevd,
         int M, int K, int epi,
         const float* __restrict__ biasf, const float* __restrict__ biasb,
         const float* __restrict__ resid, int ldr)
{
    constexpr int BN = 128;
    constexpr int TM = BM / 16;
    constexpr int NAc = (BM * BK) / 1024;  // A cp.asyncs per thread per stage
    constexpr int NBc = BK / 8;            // B cp.asyncs per thread per stage
    constexpr int ST = 3;
    __shared__ __align__(16) float As[ST][BK][BM + 4];
    __shared__ __align__(16) float Bs[ST][BK][BN + 8];

    const int s   = blockIdx.z % nsplit;
    const int dir = blockIdx.z / nsplit;
    const float* A    = (dir ? Ab : Af) + (size_t)s * K * ldm;
    const float* W    = (dir ? Wb : Wf) + (size_t)s * K * ldn;
    const float* bias = dir ? biasb : biasf;
    const int crev = crevd & -dir;
    const size_t cdo = (size_t)dir * cdoff + (size_t)s * sdoff;

    const int tid  = threadIdx.x;
    const int row0 = blockIdx.y * BM;
    const int col0 = blockIdx.x * BN;
    const int tx   = tid & 15;
    const int ty   = tid >> 4;

    u64t acc2[TM][4];
#pragma unroll
    for (int i = 0; i < TM; i++)
#pragma unroll
        for (int j = 0; j < 4; j++) acc2[i][j] = 0ull;

    auto issue = [&](int ki, int buf) {
        const int kb = ki * BK;
#pragma unroll
        for (int l = 0; l < NAc; l++) {
            int fi = tid + l * 256;
            int kk = fi / (BM / 4);
            int mc = fi % (BM / 4);
            uint32_t dst = smem_u32(&As[buf][kk][mc * 4]);
            const float* src = A + (size_t)(kb + kk) * ldm + row0 + mc * 4;
            CP_ASYNC16(dst, src);
        }
#pragma unroll
        for (int l = 0; l < NBc; l++) {
            int fi = tid + l * 256;
            int kk = fi >> 5, m = fi & 31;
            uint32_t dst = smem_u32(&Bs[buf][kk][(m >> 1) * 4 + (m & 1) * 64]);
            const float* src = W + (size_t)(kb + kk) * ldn + col0 + m * 4;
            CP_ASYNC16(dst, src);
        }
        CP_COMMIT();
    };

    const int nk = K / BK;
    issue(0, 0);
    if (nk > 1) issue(1, 1);

    for (int ki = 0; ki < nk; ki++) {
        if (ki + 1 < nk) { CP_WAIT1(); } else { CP_WAIT0(); }
        __syncthreads();
        if (ki + 2 < nk) issue(ki + 2, (ki + 2) % ST);
        const int cur = ki % ST;
#pragma unroll
        for (int kk = 0; kk < BK; kk++) {
            float a[TM];
#pragma unroll
            for (int i = 0; i < TM; i += 4)
                *reinterpret_cast<float4*>(&a[i]) =
                    *reinterpret_cast<const float4*>(&As[cur][kk][ty * TM + i]);
            u64t b2[4];
            {
                ulonglong2 bv0 = *reinterpret_cast<const ulonglong2*>(&Bs[cur][kk][tx * 4]);
                ulonglong2 bv1 = *reinterpret_cast<const ulonglong2*>(&Bs[cur][kk][64 + tx * 4]);
                b2[0] = bv0.x; b2[1] = bv0.y;
                b2[2] = bv1.x; b2[3] = bv1.y;
            }
#pragma unroll
            for (int i = 0; i < TM; i++) {
                u64t a2 = pack2(a[i], a[i]);
#pragma unroll
                for (int j = 0; j < 4; j++)
                    FFMA2(acc2[i][j], a2, b2[j], acc2[i][j]);
            }
        }
    }

#pragma unroll
    for (int i = 0; i < TM; i++) {
        int lr = row0 + ty * TM + i;
        int pr = crev ? (M - 1 - lr) : lr;
#pragma unroll
        for (int j = 0; j < 4; j++) {
            float v0, v1;
            unpack2(acc2[i][j], v0, v1);
            int c0 = col0 + tx * 8 + j * 2;
            if (epi == 1) {
                v0 = softplus_f(v0 + bias[c0]);
                v1 = softplus_f(v1 + bias[c0 + 1]);
            } else if (epi == 2) {
                v0 += resid[(size_t)pr * ldr + c0];
                v1 += resid[(size_t)pr * ldr + c0 + 1];
            } else if (epi == 3) {
                v0 += bias[c0];
                v1 += bias[c0 + 1];
            }
            C[cdo + (size_t)pr * ldc + c0]     = v0;
            C[cdo + (size_t)pr * ldc + c0 + 1] = v1;
        }
    }
}

// ---------------- out_reduce: cat[pr][dir*DM+c] = opart0+opart1 + x[pr][c] ----------------
__global__ void __launch_bounds__(256)
out_reduce(const float* __restrict__ x)
{
    int idx = blockIdx.x * blockDim.x + threadIdx.x;   // 2*1024*1024
    int c   = idx & (DM - 1);
    int t   = (idx >> 10) & (LSEQ - 1);
    int dir = idx >> 20;
    int pr  = dir ? (LSEQ - 1 - t) : t;
    float v = g_opart[dir][0][t][c] + g_opart[dir][1][t][c] + x[(size_t)pr * DM + c];
    g_cat[pr][dir * DM + c] = v;
}

// ---------------- causal depthwise conv (4 taps) + SiLU ----------------
__global__ void conv_silu_kernel(const float* __restrict__ cwf, const float* __restrict__ cbf,
                                 const float* __restrict__ cwb, const float* __restrict__ cbb)
{
    int idx = blockIdx.x * blockDim.x + threadIdx.x;
    int d   = idx & (DI - 1);
    int t   = (idx >> 11) & (LSEQ - 1);
    int dir = idx >> 21;
    const float* cw = dir ? cwb : cwf;
    const float* cb = dir ? cbb : cbf;
    float w0 = cw[d * 4 + 0], w1 = cw[d * 4 + 1], w2 = cw[d * 4 + 2], w3 = cw[d * 4 + 3];
    const float* xi = &g_xz[dir][0][d];
    float acc = cb[d];
    if (t >= 3) acc += w0 * xi[(t - 3) * (2 * DI)];
    if (t >= 2) acc += w1 * xi[(t - 2) * (2 * DI)];
    if (t >= 1) acc += w2 * xi[(t - 1) * (2 * DI)];
    acc += w3 * xi[t * (2 * DI)];
    g_u[dir][t][d] = acc * sigmoid_f(acc);
}

// ---------------- x-proj: x_dbl = u @ xproj_w^T, 16-way split-K ----------------
__global__ void __launch_bounds__(256)
xproj_partial_kernel(const float* __restrict__ wf, const float* __restrict__ wb)
{
    const int chunk = blockIdx.x;
    const int mb    = blockIdx.y;
    const int dir   = blockIdx.z;
    const float* W  = dir ? wb : wf;
    const int row0  = mb * 32;
    const int kbase = chunk * 128;
    const int tid   = threadIdx.x;

    __shared__ __align__(16) float Us[32][36];
    __shared__ __align__(16) float Ws[32][100];

    const int tx = tid & 15;
    const int ty = tid >> 4;
    float acc[2][6];
#pragma unroll
    for (int i = 0; i < 2; i++)
#pragma unroll
        for (int j = 0; j < 6; j++) acc[i][j] = 0.f;

#pragma unroll
    for (int k0 = 0; k0 < 128; k0 += 32) {
        {
            int r  = tid >> 3;
            int kk = (tid & 7) << 2;
            float4 v = *reinterpret_cast<const float4*>(&g_u[dir][row0 + r][kbase + k0 + kk]);
            Us[kk + 0][r] = v.x; Us[kk + 1][r] = v.y;
            Us[kk + 2][r] = v.z; Us[kk + 3][r] = v.w;
        }
#pragma unroll
        for (int l = 0; l < 3; l++) {
            int fi = tid + l * 256;
            int n  = fi >> 3;
            int kk = (fi & 7) << 2;
            float4 v = *reinterpret_cast<const float4*>(&W[(size_t)n * DI + kbase + k0 + kk]);
            Ws[kk + 0][n] = v.x; Ws[kk + 1][n] = v.y;
            Ws[kk + 2][n] = v.z; Ws[kk + 3][n] = v.w;
        }
        __syncthreads();
#pragma unroll
        for (int kk = 0; kk < 32; kk++) {
            float a0 = Us[kk][ty * 2 + 0];
            float a1 = Us[kk][ty * 2 + 1];
#pragma unroll
            for (int j = 0; j < 6; j++) {
                float bv = Ws[kk][tx * 6 + j];
                acc[0][j] = fmaf(a0, bv, acc[0][j]);
                acc[1][j] = fmaf(a1, bv, acc[1][j]);
            }
        }
        __syncthreads();
    }
#pragma unroll
    for (int i = 0; i < 2; i++)
#pragma unroll
        for (int j = 0; j < 6; j++)
            g_xdbl_part[dir][chunk][row0 + ty * 2 + i][tx * 6 + j] = acc[i][j];
}

__global__ void xdbl_reduce_kernel()
{
    int idx = blockIdx.x * blockDim.x + threadIdx.x;   // 2*1024*96
    int c   = idx % 96;
    int t   = (idx / 96) & (LSEQ - 1);
    int dir = idx / (96 * LSEQ);
    float s = 0.f;
#pragma unroll
    for (int ch = 0; ch < 16; ch++) s += g_xdbl_part[dir][ch][t][c];
    g_xdbl[dir][t][c] = s;
    if (c < DTR) g_xdT[dir][c][t] = s;   // k-major copy for the dt GEMM
}

// ---------------- selective scan: 4-step chunked register prefetch ----------------
__global__ void __launch_bounds__(128)
scan_kernel(const float* __restrict__ Alf, const float* __restrict__ Dpf,
            const float* __restrict__ Alb, const float* __restrict__ Dpb)
{
    int gid = blockIdx.x * 128 + threadIdx.x;   // 16384 total
    int q   = gid & 3;
    int grp = gid >> 2;
    int dir = grp >> 11;
    int d   = grp & (DI - 1);

    const float* Alog = dir ? Alb : Alf;
    float dp = (dir ? Dpb : Dpf)[d];
    float Aa[4];
#pragma unroll
    for (int j = 0; j < 4; j++) Aa[j] = -expf(Alog[d * DS + q * 4 + j]);

    const float* dep = &g_delta[dir][0][d];
    const float* up  = &g_u[dir][0][d];
    const float* zp  = &g_xz[dir][0][DI + d];
    const float* bcp = &g_xdbl[dir][0][DTR + q * 4];
    float* ypT = &g_y2T[dir][d][0];

    float h0 = 0.f, h1 = 0.f, h2 = 0.f, h3 = 0.f;

    float dA[4], uA[4], zA[4]; float4 BA[4], CA[4];
    float dB[4], uB[4], zB[4]; float4 BB[4], CB[4];

#define LOADCH(t0, dv, uv, zv, Bv, Cv) do {                                   \
    _Pragma("unroll")                                                         \
    for (int i = 0; i < 4; i++) {                                             \
        dv[i] = dep[((t0) + i) * DI];                                         \
        uv[i] = up [((t0) + i) * DI];                                         \
        zv[i] = zp [((t0) + i) * (2 * DI)];                                   \
        Bv[i] = *reinterpret_cast<const float4*>(bcp + ((t0) + i) * 96);      \
        Cv[i] = *reinterpret_cast<const float4*>(bcp + ((t0) + i) * 96 + DS); \
    } } while (0)

#define COMPCH(t0, dv, uv, zv, Bv, Cv) do {                                   \
    float yout[4];                                                            \
    _Pragma("unroll")                                                         \
    for (int i = 0; i < 4; i++) {                                             \
        float dc = dv[i], uc = uv[i], zc = zv[i];                             \
        float4 Bc = Bv[i], Cc = Cv[i];                                        \
        float db = dc * uc;                                                   \
        float e0 = __expf(dc * Aa[0]);                                        \
        float e1 = __expf(dc * Aa[1]);                                        \
        float e2 = __expf(dc * Aa[2]);                                        \
        float e3 = __expf(dc * Aa[3]);                                        \
        h0 = fmaf(e0, h0, db * Bc.x);                                         \
        h1 = fmaf(e1, h1, db * Bc.y);                                         \
        h2 = fmaf(e2, h2, db * Bc.z);                                         \
        h3 = fmaf(e3, h3, db * Bc.w);                                         \
        float p = h0 * Cc.x + h1 * Cc.y + h2 * Cc.z + h3 * Cc.w;              \
        p += __shfl_xor_sync(0xffffffffu, p, 1);                              \
        p += __shfl_xor_sync(0xffffffffu, p, 2);                              \
        if (q == 0) yout[i] = (p + uc * dp) * zc * sigmoid_f(zc);             \
    }                                                                         \
    if (q == 0) {                                                             \
        float4 v; v.x = yout[0]; v.y = yout[1]; v.z = yout[2]; v.w = yout[3]; \
        *reinterpret_cast<float4*>(ypT + (t0)) = v;                           \
    } } while (0)

    LOADCH(0, dA, uA, zA, BA, CA);
    for (int c = 0; c < LSEQ / 4; c += 2) {
        if (c + 1 < LSEQ / 4) LOADCH((c + 1) * 4, dB, uB, zB, BB, CB);
        COMPCH(c * 4, dA, uA, zA, BA, CA);
        if (c + 2 < LSEQ / 4) LOADCH((c + 2) * 4, dA, uA, zA, BA, CA);
        COMPCH((c + 1) * 4, dB, uB, zB, BB, CB);
    }
#undef LOADCH
#undef COMPCH
}

// ---------------- layernorm fused with final-proj split-K reduce ----------------
__global__ void __launch_bounds__(256)
layernorm_kernel(const float* __restrict__ pbias,
                 const float* __restrict__ lw, const float* __restrict__ lb,
                 float* __restrict__ out)
{
    int row = blockIdx.x;
    float vr[4];
    float s = 0.f, s2 = 0.f;
#pragma unroll
    for (int l = 0; l < 4; l++) {
        int i = threadIdx.x + l * 256;
        float v = pbias[i]
                + g_fpart[0][row][i] + g_fpart[1][row][i]
                + g_fpart[2][row][i] + g_fpart[3][row][i];
        vr[l] = v;
        s += v; s2 += v * v;
    }
#pragma unroll
    for (int o = 16; o > 0; o >>= 1) {
        s  += __shfl_xor_sync(0xffffffffu, s,  o);
        s2 += __shfl_xor_sync(0xffffffffu, s2, o);
    }
    __shared__ float sm1[8], sm2[8];
    __shared__ float mu_s, rs_s;
    int w = threadIdx.x >> 5;
    if ((threadIdx.x & 31) == 0) { sm1[w] = s; sm2[w] = s2; }
    __syncthreads();
    if (threadIdx.x == 0) {
        float S = 0.f, S2 = 0.f;
#pragma unroll
        for (int i = 0; i < 8; i++) { S += sm1[i]; S2 += sm2[i]; }
        float mu  = S * (1.f / DM);
        float var = S2 * (1.f / DM) - mu * mu;
        mu_s = mu;
        rs_s = rsqrtf(var + 1e-5f);
    }
    __syncthreads();
    float mu = mu_s, rs = rs_s;
#pragma unroll
    for (int l = 0; l < 4; l++) {
        int i = threadIdx.x + l * 256;
        out[(size_t)row * DM + i] = (vr[l] - mu) * rs * lw[i] + lb[i];
    }
}

// ---------------- launch ----------------
extern "C" void kernel_launch(void* const* d_in, const int* in_sizes, int n_in,
                              void* d_out, int out_size)
{
    const float* x         = (const float*)d_in[0];
    const float* fw_in_w   = (const float*)d_in[1];
    const float* fw_conv_w = (const float*)d_in[2];
    const float* fw_conv_b = (const float*)d_in[3];
    const float* fw_xproj  = (const float*)d_in[4];
    const float* fw_dt_w   = (const float*)d_in[5];
    const float* fw_dt_b   = (const float*)d_in[6];
    const float* fw_Alog   = (const float*)d_in[7];
    const float* fw_Dp     = (const float*)d_in[8];
    const float* fw_out_w  = (const float*)d_in[9];
    const float* bw_in_w   = (const float*)d_in[10];
    const float* bw_conv_w = (const float*)d_in[11];
    const float* bw_conv_b = (const float*)d_in[12];
    const float* bw_xproj  = (const float*)d_in[13];
    const float* bw_dt_w   = (const float*)d_in[14];
    const float* bw_dt_b   = (const float*)d_in[15];
    const float* bw_Alog   = (const float*)d_in[16];
    const float* bw_Dp     = (const float*)d_in[17];
    const float* bw_out_w  = (const float*)d_in[18];
    const float* proj_w    = (const float*)d_in[19];
    const float* proj_b    = (const float*)d_in[20];
    const float* ln_w      = (const float*)d_in[21];
    const float* ln_b      = (const float*)d_in[22];
    float* out = (float*)d_out;

    float *xz, *del, *xT, *xrevT, *inwT, *outwT, *pwT, *dtwT, *xdT, *y2T, *catT, *opart, *fpart;
    cudaGetSymbolAddress((void**)&xz,    g_xz);
    cudaGetSymbolAddress((void**)&del,   g_delta);
    cudaGetSymbolAddress((void**)&xT,    g_xT);
    cudaGetSymbolAddress((void**)&xrevT, g_xrevT);
    cudaGetSymbolAddress((void**)&inwT,  g_inwT);
    cudaGetSymbolAddress((void**)&outwT, g_outwT);
    cudaGetSymbolAddress((void**)&pwT,   g_pwT);
    cudaGetSymbolAddress((void**)&dtwT,  g_dtwT);
    cudaGetSymbolAddress((void**)&xdT,   g_xdT);
    cudaGetSymbolAddress((void**)&y2T,   g_y2T);
    cudaGetSymbolAddress((void**)&catT,  g_catT);
    cudaGetSymbolAddress((void**)&opart, g_opart);
    cudaGetSymbolAddress((void**)&fpart, g_fpart);

    const size_t INW = (size_t)DM * 2 * DI;
    const size_t OUTW = (size_t)DI * DM;
    const size_t DTW = (size_t)DTR * DI;
    const size_t XDT = (size_t)DTR * LSEQ;
    const size_t Y2T = (size_t)DI * LSEQ;
    const size_t PLANE = (size_t)LSEQ * DM;

    // 0) all input transposes in one launch
    transpose_all<<<16640, 256>>>(x, fw_in_w, bw_in_w, fw_out_w, bw_out_w,
                                  proj_w, fw_dt_w, bw_dt_w);
    // 1,2) anchors so in_proj sits at profiler capture point (idx 3)
    noop_kernel<<<1, 32>>>();
    noop_kernel<<<1, 32>>>();

    // 3) in_proj: (M=1024, N=4096, K=1024), fw+bw merged
    sgemm_ca<128,32,2><<<dim3(32, 8, 2), 256>>>(
        xT, xrevT, LSEQ, inwT, inwT + INW, 2 * DI,
        xz, (size_t)LSEQ * 2 * DI, 0, 1, 2 * DI, 0,
        LSEQ, DM, 0, nullptr, nullptr, nullptr, 0);

    // 4) conv + silu -> u
    conv_silu_kernel<<<(2 * LSEQ * DI) / 256, 256>>>(fw_conv_w, fw_conv_b, bw_conv_w, bw_conv_b);

    // 5) x-proj (16-way split-K) -> x_dbl (+ k-major dt cols)
    dim3 gx(16, 32, 2);
    xproj_partial_kernel<<<gx, 256>>>(fw_xproj, bw_xproj);
    xdbl_reduce_kernel<<<(2 * LSEQ * 96) / 256, 256>>>();

    // 6) delta = softplus(dt @ dt_w^T + dt_b)  (M=1024, N=2048, K=64)
    sgemm_ca<128,32,2><<<dim3(16, 8, 2), 256>>>(
        xdT, xdT + XDT, LSEQ, dtwT, dtwT + DTW, DI,
        del, (size_t)LSEQ * DI, 0, 1, DI, 0,
        LSEQ, DTR, 1, fw_dt_b, bw_dt_b, nullptr, 0);

    // 7) selective scan -> y2^T
    scan_kernel<<<128, 128>>>(fw_Alog, fw_Dp, bw_Alog, bw_Dp);

    // 8) out_proj split-K2 -> opart  (z = dir*2 + s; per-split K=1024)
    sgemm_ca<128,32,2><<<dim3(8, 8, 4), 256>>>(
        y2T, y2T + Y2T, LSEQ, outwT, outwT + OUTW, DM,
        opart, 2 * PLANE, PLANE, 2, DM, 0,
        LSEQ, DI / 2, 0, nullptr, nullptr, nullptr, 0);

    // 9) reduce partials + residual (row-flip for bw) -> cat
    out_reduce<<<(2 * LSEQ * DM) / 256, 256>>>(x);

    // 10) cat -> catT
    transpose_cat<<<2048, 256>>>();

    // 11) final proj split-K4 -> fpart  (M=1024, N=1024, per-split K=512)
    sgemm_ca<128,32,2><<<dim3(8, 8, 4), 256>>>(
        catT, catT, LSEQ, pwT, pwT, DM,
        fpart, 0, PLANE, 4, DM, 0,
        LSEQ, 2 * DM / 4, 0, nullptr, nullptr, nullptr, 0);

    // 12) layernorm (fused split-K reduce + bias) -> out
    layernorm_kernel<<<LSEQ, 256>>>(proj_b, ln_w, ln_b, out);
}